// round 14
// baseline (speedup 1.0000x reference)
#include <cuda_runtime.h>
#include <cuda_fp16.h>
#include <math.h>
#include <stdint.h>

#define TIN 6
#define HIN 40
#define WIN 40
#define TOUT 12
#define HOUT 80
#define WOUT 80
#define NPOS 9600    // 6*40*40
#define NVOX 76800   // 12*80*80
#define GC 539

typedef unsigned long long u64;

__device__ __forceinline__ u64 pack2(float v) {
    u64 r; asm("mov.b64 %0, {%1, %1};" : "=l"(r) : "f"(v)); return r;
}
__device__ __forceinline__ void fma2(u64& d, u64 a, u64 b) {
    asm("fma.rn.f32x2 %0, %1, %2, %0;" : "+l"(d) : "l"(a), "l"(b));
}
union F4U { float4 f4; u64 u[2]; float f[4]; };
union H2U { __half2 h2; unsigned int u; };

__device__ __forceinline__ unsigned int h2_bits(__half2 h) {
    H2U x; x.h2 = h; return x.u;
}
__device__ __forceinline__ __half2 bits_h2(unsigned int b) {
    H2U x; x.u = b; return x.h2;
}

__device__ __forceinline__ uint32_t smem_u32(const void* p) {
    uint32_t a;
    asm("{ .reg .u64 t; cvta.to.shared.u64 t, %1; cvt.u32.u64 %0, t; }" : "=r"(a) : "l"(p));
    return a;
}
__device__ __forceinline__ void ldm_x4(uint32_t& r0, uint32_t& r1, uint32_t& r2, uint32_t& r3,
                                       uint32_t addr) {
    asm volatile("ldmatrix.sync.aligned.m8n8.x4.shared.b16 {%0,%1,%2,%3}, [%4];"
                 : "=r"(r0), "=r"(r1), "=r"(r2), "=r"(r3) : "r"(addr));
}
__device__ __forceinline__ void mma_16816(float* c, const uint32_t* a, const uint32_t* b) {
    asm volatile(
        "mma.sync.aligned.m16n8k16.row.col.f32.f16.f16.f32 "
        "{%0,%1,%2,%3}, {%4,%5,%6,%7}, {%8,%9}, {%0,%1,%2,%3};"
        : "+f"(c[0]), "+f"(c[1]), "+f"(c[2]), "+f"(c[3])
        : "r"(a[0]), "r"(a[1]), "r"(a[2]), "r"(a[3]), "r"(b[0]), "r"(b[1]));
}

__device__ __forceinline__ __half2 tanh2(__half2 x) {
    H2U a, b; a.h2 = x;
    asm("tanh.approx.f16x2 %0, %1;" : "=r"(b.u) : "r"(a.u));
    return b.h2;
}
__device__ __forceinline__ __half2 gelu_h2(__half2 x) {
    const __half2 K   = __float2half2_rn(0.044715f);
    const __half2 ONE = __float2half2_rn(1.0f);
    const __half2 C   = __float2half2_rn(0.7978845608028654f);
    const __half2 H   = __float2half2_rn(0.5f);
    __half2 u  = __hmul2(x, x);
    __half2 v  = __hfma2(K, u, ONE);
    __half2 z  = __hmul2(__hmul2(C, x), v);
    __half2 th = tanh2(z);
    return __hmul2(__hmul2(H, x), __hadd2(th, ONE));
}

// ---------------- scratch ----------------
__device__ __align__(16) __half d_Qh[8 * NPOS * 256];
__device__ __align__(16) __half d_featTh[NPOS * 64];
__device__ __align__(16) __half d_QwTh[8 * 256 * 64];
__device__ __align__(16) float d_b1[256];
__device__ __align__(16) float d_C6[256 * 6];
__device__ __align__(16) float d_bf[256];
__device__ __align__(16) float d_C6f[6 * 256];
__device__ __align__(16) float d_sc3[3 * NPOS];
__device__ __align__(16) float4 d_g4[172];

// =====================================================================
// Launch 1: prep (role blocks)
// =====================================================================
__global__ void __launch_bounds__(256) k_prep(
    const float* __restrict__ feat,
    const float* __restrict__ dw1_w, const float* __restrict__ dw1_b,
    const float* __restrict__ pw1_w, const float* __restrict__ pw1_b,
    const float* __restrict__ sc_dw_w, const float* __restrict__ sc_dw_b,
    const float* __restrict__ sc_pw_w, const float* __restrict__ sc_pw_b,
    const float* __restrict__ fc1_w)
{
    __shared__ float sbuf[4160];
    int b = blockIdx.x;
    int tid = threadIdx.x;

    if (b < 150) {                       // featT fp16 transpose
        float* s = sbuf;
        int p0 = b * 64;
        #pragma unroll
        for (int r = 0; r < 16; r++) {
            int idx = r * 256 + tid;
            int c = idx >> 6, p = idx & 63;
            s[c * 65 + p] = feat[c * NPOS + p0 + p];
        }
        __syncthreads();
        __half2* outp = (__half2*)d_featTh;
        #pragma unroll
        for (int r = 0; r < 8; r++) {
            int idx = r * 256 + tid;
            int p = idx >> 5, cc = idx & 31;
            outp[(p0 + p) * 32 + cc] =
                __floats2half2_rn(s[(2 * cc) * 65 + p], s[(2 * cc + 1) * 65 + p]);
        }
        return;
    }
    if (b == 150) {                      // geometry
        int k = tid;
        const int nout[3] = {TOUT, HOUT, WOUT};
        const int nin[3]  = {TIN, HIN, WIN};
        const int off[3]  = {0, 12, 92};
        for (int a = 0; a < 3; a++) {
            if (k >= nout[a]) continue;
            float n_o = (float)nout[a];
            int   ni  = nin[a];
            float n_i = (float)ni;
            float ro = 1.0f / n_o;
            float ri = 1.0f / n_i;
            float c = (-1.0f + ro) + (2.0f * ro) * (float)k;
            float dm = 0.0f, dp = 0.0f;
            int im = 0, ip = 0;
            for (int s = 0; s < 2; s++) {
                float sv = s ? 1.0f : -1.0f;
                float cc = (c + sv * ri) + 1e-6f;
                cc = fminf(fmaxf(cc, -1.0f + 1e-6f), 1.0f - 1e-6f);
                float v = ((cc + 1.0f) * n_i - 1.0f) * 0.5f;
                int idx = (int)rintf(v);
                idx = min(max(idx, 0), ni - 1);
                float l = (-1.0f + ri) + (2.0f * ri) * (float)idx;
                float d = (c - l) * n_i;
                if (s == 0) { im = idx; dm = d; }
                else        { ip = idx; dp = d; }
            }
            float x = ((c + 1.0f) * n_i - 1.0f) * 0.5f;
            x = fminf(fmaxf(x, 0.0f), n_i - 1.0f);
            float x0 = floorf(x);
            int i0 = (int)x0;
            int i1 = min(i0 + 1, ni - 1);
            int pk = im | (ip << 8) | (i0 << 16) | (i1 << 24);
            d_g4[off[a] + k] = make_float4(dm, dp, x - x0, __int_as_float(pk));
        }
        return;
    }
    if (b < 183) {                       // fold_bias
        int lane = tid & 31;
        int o = (b - 151) * 8 + (tid >> 5);
        const float* row = pw1_w + o * GC;
        float s = 0.0f;
        for (int g = lane; g < GC; g += 32) s += row[g] * dw1_b[g];
        float vc = 0.0f; int bucket = -1;
        if (lane < 24) {
            int i = lane / 3, r = lane % 3;
            vc = row[lane] * dw1_w[lane];
            int st = (i >> 2) & 1, sx = (i >> 1) & 1, sy = i & 1;
            bucket = (r == 0) ? st : (r == 1) ? 2 + sx : 4 + sy;
        }
        float s2 = (lane < 3) ? row[536 + lane] * dw1_w[536 + lane] : 0.0f;
        #pragma unroll
        for (int m = 16; m; m >>= 1) {
            s  += __shfl_xor_sync(0xffffffffu, s,  m);
            s2 += __shfl_xor_sync(0xffffffffu, s2, m);
        }
        #pragma unroll
        for (int k = 0; k < 6; k++) {
            float mval = (bucket == k) ? vc : 0.0f;
            #pragma unroll
            for (int m = 16; m; m >>= 1) mval += __shfl_xor_sync(0xffffffffu, mval, m);
            if (lane == 0) d_C6[o * 6 + k] = mval;
        }
        if (lane == 0) d_b1[o] = pw1_b[o] + s + 2.0f * s2;
        return;
    }
    if (b < 221) {                       // skip branch pointwise
        float* shp = sbuf;
        if (tid < 192) shp[tid] = sc_pw_w[tid] * sc_dw_w[tid & 63];
        if (tid < 3) {
            float bb = sc_pw_b[tid];
            for (int c = 0; c < 64; c++) bb += sc_pw_w[tid * 64 + c] * sc_dw_b[c];
            shp[192 + tid] = bb;
        }
        __syncthreads();
        int pos = (b - 183) * 256 + tid;
        if (pos >= NPOS) return;
        float a0 = shp[192], a1 = shp[193], a2 = shp[194];
        for (int c = 0; c < 64; c++) {
            float v = feat[c * NPOS + pos];
            a0 += shp[c] * v; a1 += shp[64 + c] * v; a2 += shp[128 + c] * v;
        }
        d_sc3[pos] = a0; d_sc3[NPOS + pos] = a1; d_sc3[2 * NPOS + pos] = a2;
        return;
    }
    // QwT fold GEMM
    {
        int bb = b - 221;
        float* As  = sbuf;
        float* Bst = sbuf + 1056;
        float* sdw = sbuf + 2112;
        int ic0 = (bb & 15) * 32;
        int o20 = (bb >> 4) * 32;
        if (tid < 32) sdw[tid] = dw1_w[24 + ic0 + tid];
        __syncthreads();
        float acc[4] = {0, 0, 0, 0};
        int ic_l = tid & 31;
        int o2g  = tid >> 5;
        for (int ko = 0; ko < 256; ko += 32) {
            #pragma unroll
            for (int m = 0; m < 4; m++) {
                int e = m * 256 + tid;
                int o = e >> 5, ic = e & 31;
                As[o * 33 + ic] = pw1_w[(ko + o) * GC + 24 + ic0 + ic] * sdw[ic];
                Bst[o * 33 + ic] = fc1_w[(o20 + o) * 256 + ko + ic];
            }
            __syncthreads();
            #pragma unroll 8
            for (int o = 0; o < 32; o++) {
                float a = As[o * 33 + ic_l];
                #pragma unroll
                for (int j = 0; j < 4; j++)
                    acc[j] += a * Bst[(o2g * 4 + j) * 33 + o];
            }
            __syncthreads();
        }
        int ic = ic0 + ic_l;
        int slot = ic >> 6, c = ic & 63;
        #pragma unroll
        for (int j = 0; j < 4; j++) {
            int o2 = o20 + o2g * 4 + j;
            d_QwTh[(slot * 256 + o2) * 64 + c] = __float2half_rn(acc[j]);
        }
    }
}

// =====================================================================
// Launch 2: phaseA (HMMA) + fold2 rider block
// =====================================================================
__global__ void __launch_bounds__(256) k_phaseA_mma(const float* __restrict__ fc1_w,
                                                    const float* __restrict__ fc1_b) {
    __shared__ __align__(16) char smem_buf[34816];
    __half* sA = (__half*)smem_buf;
    __half* sB = (__half*)(smem_buf + 16384);
    int tid = threadIdx.x;
    int b = blockIdx.x;

    if (b == 1200) {                     // fold2 rider
        float* sb1 = (float*)smem_buf;
        float* sc6 = (float*)smem_buf + 256;
        int o2 = tid;
        sb1[o2] = d_b1[o2];
        for (int idx = o2; idx < 1536; idx += 256) sc6[idx] = d_C6[idx];
        __syncthreads();
        float bf = fc1_b[o2];
        float c6f[6] = {0, 0, 0, 0, 0, 0};
        const float* frow = fc1_w + o2 * 256;
        for (int o = 0; o < 256; o++) {
            float f = frow[o];
            bf += f * sb1[o];
            #pragma unroll
            for (int kk = 0; kk < 6; kk++) c6f[kk] += f * sc6[o * 6 + kk];
        }
        d_bf[o2] = bf;
        #pragma unroll
        for (int kk = 0; kk < 6; kk++) d_C6f[kk * 256 + o2] = c6f[kk];
        return;
    }

    int lane = tid & 31;
    int wid = tid >> 5;
    int p_tile = b % 75;
    int n_half = (b / 75) & 1;
    int slot = b / 150;
    int p0 = p_tile * 128;
    int n0 = n_half * 128;

    const uint4* gA = (const uint4*)(d_featTh + (size_t)p0 * 64);
    const uint4* gB = (const uint4*)(d_QwTh + (size_t)(slot * 256 + n0) * 64);
    #pragma unroll
    for (int r = 0; r < 4; r++) {
        int idx = r * 256 + tid;
        int row = idx >> 3, ck = idx & 7;
        int sck = ck ^ (row & 7);
        *(uint4*)&sA[row * 64 + sck * 8] = gA[idx];
        *(uint4*)&sB[row * 64 + sck * 8] = gB[idx];
    }
    __syncthreads();

    int wm = (wid & 3) * 32;
    int wn = (wid >> 2) * 64;
    uint32_t baseA = smem_u32(sA);
    uint32_t baseB = smem_u32(sB);

    float acc[2][8][4];
    #pragma unroll
    for (int mi = 0; mi < 2; mi++)
        #pragma unroll
        for (int j = 0; j < 8; j++)
            #pragma unroll
            for (int q = 0; q < 4; q++) acc[mi][j][q] = 0.0f;

    #pragma unroll
    for (int ks = 0; ks < 4; ks++) {
        int kc = ks * 2;
        uint32_t a[2][4];
        #pragma unroll
        for (int mi = 0; mi < 2; mi++) {
            int row = wm + mi * 16 + (lane & 15);
            int ck = (kc + (lane >> 4)) ^ (row & 7);
            ldm_x4(a[mi][0], a[mi][1], a[mi][2], a[mi][3],
                   baseA + (uint32_t)(row * 64 + ck * 8) * 2);
        }
        uint32_t bfr[8][2];
        #pragma unroll
        for (int jp = 0; jp < 4; jp++) {
            int row = wn + jp * 16 + ((lane >> 4) & 1) * 8 + (lane & 7);
            int ck = (kc + ((lane >> 3) & 1)) ^ (row & 7);
            ldm_x4(bfr[2 * jp][0], bfr[2 * jp][1], bfr[2 * jp + 1][0], bfr[2 * jp + 1][1],
                   baseB + (uint32_t)(row * 64 + ck * 8) * 2);
        }
        #pragma unroll
        for (int mi = 0; mi < 2; mi++)
            #pragma unroll
            for (int j = 0; j < 8; j++)
                mma_16816(acc[mi][j], a[mi], bfr[j]);
    }

    __syncthreads();
    __half2* sOut = (__half2*)smem_buf;
    #pragma unroll
    for (int mi = 0; mi < 2; mi++) {
        int r0 = wm + mi * 16 + (lane >> 2);
        int c2 = (wn >> 1) + (lane & 3);
        #pragma unroll
        for (int j = 0; j < 8; j++) {
            sOut[r0 * 68 + c2 + j * 4]       = __floats2half2_rn(acc[mi][j][0], acc[mi][j][1]);
            sOut[(r0 + 8) * 68 + c2 + j * 4] = __floats2half2_rn(acc[mi][j][2], acc[mi][j][3]);
        }
    }
    __syncthreads();
    const __half* sH = (const __half*)smem_buf;
    #pragma unroll
    for (int it = 0; it < 8; it++) {
        int idx = it * 256 + tid;
        int row = idx >> 4, u4 = idx & 15;
        uint4 v = *(const uint4*)(sH + row * 136 + u4 * 8);
        *(uint4*)(d_Qh + (((size_t)(slot * NPOS + p0 + row)) << 8) + n0 + u4 * 8) = v;
    }
}

// =====================================================================
// combine v5: R9 structure, fc2 + C6f[4,5] in smem, 3 blocks/SM
// =====================================================================
__global__ void __launch_bounds__(256, 3) k_combine(const float* __restrict__ fc2_w,
                                                    const float* __restrict__ fc2_b,
                                                    float* __restrict__ out) {
    __shared__ __align__(16) float s_fc2[3 * 256];
    __shared__ __align__(16) float s_c45[2 * 256];
    {
        int tid = threadIdx.x;
        #pragma unroll
        for (int r = 0; r < 3; r++) s_fc2[r * 256 + tid] = fc2_w[r * 256 + tid];
        s_c45[tid]       = d_C6f[4 * 256 + tid];
        s_c45[256 + tid] = d_C6f[5 * 256 + tid];
    }
    __syncthreads();

    int lane = threadIdx.x & 31;
    int W = blockIdx.x * 8 + (threadIdx.x >> 5);
    int t = W / 400;
    int rem = W - t * 400;
    int h = rem / 5;
    int w0 = (rem - h * 5) * 16;
    int ch = lane * 8;

    F4U bf0, bf1;
    bf0.f4 = *(const float4*)&d_bf[ch];
    bf1.f4 = *(const float4*)&d_bf[ch + 4];
    float obl = 0.0f;
    if (lane == 0)       obl = fc2_b[0];
    else if (lane == 8)  obl = fc2_b[1];
    else if (lane == 16) obl = fc2_b[2];

    float4 gt = d_g4[t];
    float4 gh = d_g4[12 + h];
    int pkt = __float_as_int(gt.w);
    int pkh = __float_as_int(gh.w);
    int it0 = pkt & 255, it1 = (pkt >> 8) & 255, lt0 = (pkt >> 16) & 255, lt1 = (pkt >> 24) & 255;
    int ih0 = pkh & 255, ih1 = (pkh >> 8) & 255, lh0 = (pkh >> 16) & 255, lh1 = (pkh >> 24) & 255;
    float dtm = gt.x, dtp = gt.y, ft = gt.z;
    float dhm = gh.x, dhp = gh.y, fh = gh.z;
    float at0 = fabsf(dtm), at1 = fabsf(dtp);
    float ah0 = fabsf(dhm), ah1 = fabsf(dhp);
    float atah[4] = {at0 * ah0, at0 * ah1, at1 * ah0, at1 * ah1};
    int bth[4] = {(it0 * HIN + ih0) * WIN, (it0 * HIN + ih1) * WIN,
                  (it1 * HIN + ih0) * WIN, (it1 * HIN + ih1) * WIN};

    // prologue: t/h rel-coord terms (fp32 fma2, rows 0..3 transient from global)
    F4U P0 = bf0, P1 = bf1;
    {
        u64 dv[4] = {pack2(dtm), pack2(dtp), pack2(dhm), pack2(dhp)};
        #pragma unroll
        for (int kk = 0; kk < 4; kk++) {
            F4U ca, cb;
            ca.f4 = *(const float4*)&d_C6f[kk * 256 + ch];
            cb.f4 = *(const float4*)&d_C6f[kk * 256 + ch + 4];
            fma2(P0.u[0], dv[kk], ca.u[0]); fma2(P0.u[1], dv[kk], ca.u[1]);
            fma2(P1.u[0], dv[kk], cb.u[0]); fma2(P1.u[1], dv[kk], cb.u[1]);
        }
    }

    int jt = (lane >> 2) & 1, jh = (lane >> 1) & 1, jw = lane & 1;
    int p_th = ((jt ? lt1 : lt0) * HIN + (jh ? lh1 : lh0)) * WIN;
    float wt_th = (jt ? ft : 1.0f - ft) * (jh ? fh : 1.0f - fh);

    int vbase = (t * HOUT + h) * WOUT + w0;

    for (int k = 0; k < 16; k++) {
        int w = w0 + k;
        float4 gw = d_g4[92 + w];
        int pkw = __float_as_int(gw.w);
        int iw0 = pkw & 255, iw1 = (pkw >> 8) & 255;
        int lw0 = (pkw >> 16) & 255, lw1 = (pkw >> 24) & 255;
        float dwm = gw.x, dwp = gw.y, fw = gw.z;
        float aw0f = fabsf(dwm), aw1f = fabsf(dwp);

        float area[8]; int pos[8]; float tot = 0.0f;
        #pragma unroll
        for (int i = 0; i < 8; i++) {
            float aa = atah[i >> 1] * ((i & 1) ? aw1f : aw0f) + 1e-9f;
            area[i] = aa; tot += aa;
            pos[i] = bth[i >> 1] + ((i & 1) ? iw1 : iw0);
        }
        float rtot = 1.0f / tot;

        // A = P + dwm*C6f[4] + dwp*C6f[5]  (coeffs from smem)
        F4U A0 = P0, A1 = P1;
        {
            u64 am = pack2(dwm), ap = pack2(dwp);
            F4U c4lo, c4hi, c5lo, c5hi;
            c4lo.f4 = *(const float4*)&s_c45[ch];
            c4hi.f4 = *(const float4*)&s_c45[ch + 4];
            c5lo.f4 = *(const float4*)&s_c45[256 + ch];
            c5hi.f4 = *(const float4*)&s_c45[256 + ch + 4];
            fma2(A0.u[0], am, c4lo.u[0]); fma2(A0.u[1], am, c4lo.u[1]);
            fma2(A1.u[0], am, c4hi.u[0]); fma2(A1.u[1], am, c4hi.u[1]);
            fma2(A0.u[0], ap, c5lo.u[0]); fma2(A0.u[1], ap, c5lo.u[1]);
            fma2(A1.u[0], ap, c5hi.u[0]); fma2(A1.u[1], ap, c5hi.u[1]);
        }

        __half2 hacc0 = __float2half2_rn(0.0f), hacc1 = hacc0, hacc2 = hacc0, hacc3 = hacc0;
        #pragma unroll
        for (int i = 0; i < 8; i++) {
            __half2 wp = __float2half2_rn(area[7 - i]);
            uint4 qv = *(const uint4*)(d_Qh + ((size_t)(i * NPOS + pos[i]) << 8) + ch);
            hacc0 = __hfma2(bits_h2(qv.x), wp, hacc0);
            hacc1 = __hfma2(bits_h2(qv.y), wp, hacc1);
            hacc2 = __hfma2(bits_h2(qv.z), wp, hacc2);
            hacc3 = __hfma2(bits_h2(qv.w), wp, hacc3);
        }
        float2 qf0 = __half22float2(hacc0);
        float2 qf1 = __half22float2(hacc1);
        float2 qf2 = __half22float2(hacc2);
        float2 qf3 = __half22float2(hacc3);
        __half2 xh0 = __floats2half2_rn(fmaf(qf0.x, rtot, A0.f[0]), fmaf(qf0.y, rtot, A0.f[1]));
        __half2 xh1 = __floats2half2_rn(fmaf(qf1.x, rtot, A0.f[2]), fmaf(qf1.y, rtot, A0.f[3]));
        __half2 xh2 = __floats2half2_rn(fmaf(qf2.x, rtot, A1.f[0]), fmaf(qf2.y, rtot, A1.f[1]));
        __half2 xh3 = __floats2half2_rn(fmaf(qf3.x, rtot, A1.f[2]), fmaf(qf3.y, rtot, A1.f[3]));
        float2 g0 = __half22float2(gelu_h2(xh0));
        float2 g1 = __half22float2(gelu_h2(xh1));
        float2 g2 = __half22float2(gelu_h2(xh2));
        float2 g3 = __half22float2(gelu_h2(xh3));

        float4 wa, wb;
        wa = *(const float4*)&s_fc2[0 * 256 + ch]; wb = *(const float4*)&s_fc2[0 * 256 + ch + 4];
        float s0 = wa.x * g0.x + wa.y * g0.y + wa.z * g1.x + wa.w * g1.y
                 + wb.x * g2.x + wb.y * g2.y + wb.z * g3.x + wb.w * g3.y;
        wa = *(const float4*)&s_fc2[1 * 256 + ch]; wb = *(const float4*)&s_fc2[1 * 256 + ch + 4];
        float s1 = wa.x * g0.x + wa.y * g0.y + wa.z * g1.x + wa.w * g1.y
                 + wb.x * g2.x + wb.y * g2.y + wb.z * g3.x + wb.w * g3.y;
        wa = *(const float4*)&s_fc2[2 * 256 + ch]; wb = *(const float4*)&s_fc2[2 * 256 + ch + 4];
        float s2 = wa.x * g0.x + wa.y * g0.y + wa.z * g1.x + wa.w * g1.y
                 + wb.x * g2.x + wb.y * g2.y + wb.z * g3.x + wb.w * g3.y;

        if (lane < 8) {
            float wt = wt_th * (jw ? fw : 1.0f - fw);
            int p = p_th + (jw ? lw1 : lw0);
            s0 += wt * d_sc3[p];
            s1 += wt * d_sc3[NPOS + p];
            s2 += wt * d_sc3[2 * NPOS + p];
        }
        s0 += __shfl_xor_sync(0xffffffffu, s0, 16);
        s1 += __shfl_xor_sync(0xffffffffu, s1, 16);
        s2 += __shfl_xor_sync(0xffffffffu, s2, 16);
        s0 += __shfl_xor_sync(0xffffffffu, s0, 8);
        s1 += __shfl_xor_sync(0xffffffffu, s1, 8);
        s2 += __shfl_xor_sync(0xffffffffu, s2, 8);
        float v = (lane < 8) ? s0 : ((lane < 16) ? s1 : s2);
        v += __shfl_xor_sync(0xffffffffu, v, 4);
        v += __shfl_xor_sync(0xffffffffu, v, 2);
        v += __shfl_xor_sync(0xffffffffu, v, 1);
        if ((lane & 7) == 0 && lane < 24) {
            out[(lane >> 3) * NVOX + vbase + k] = v + obl;
        }
    }
}

extern "C" void kernel_launch(void* const* d_in, const int* in_sizes, int n_in,
                              void* d_out, int out_size) {
    const float* feat    = (const float*)d_in[0];
    const float* dw1_w   = (const float*)d_in[1];
    const float* dw1_b   = (const float*)d_in[2];
    const float* pw1_w   = (const float*)d_in[3];
    const float* pw1_b   = (const float*)d_in[4];
    const float* fc1_w   = (const float*)d_in[5];
    const float* fc1_b   = (const float*)d_in[6];
    const float* fc2_w   = (const float*)d_in[7];
    const float* fc2_b   = (const float*)d_in[8];
    const float* sc_dw_w = (const float*)d_in[9];
    const float* sc_dw_b = (const float*)d_in[10];
    const float* sc_pw_w = (const float*)d_in[11];
    const float* sc_pw_b = (const float*)d_in[12];
    float* out = (float*)d_out;

    k_prep<<<349, 256>>>(feat, dw1_w, dw1_b, pw1_w, pw1_b,
                         sc_dw_w, sc_dw_b, sc_pw_w, sc_pw_b, fc1_w);
    k_phaseA_mma<<<1201, 256>>>(fc1_w, fc1_b);
    k_combine<<<600, 256>>>(fc2_w, fc2_b, out);
}

// round 15
// speedup vs baseline: 1.8322x; 1.8322x over previous
#include <cuda_runtime.h>
#include <cuda_fp16.h>
#include <math.h>
#include <stdint.h>

#define TIN 6
#define HIN 40
#define WIN 40
#define TOUT 12
#define HOUT 80
#define WOUT 80
#define NPOS 9600    // 6*40*40
#define NVOX 76800   // 12*80*80
#define GC 539

typedef unsigned long long u64;

// packed fp32x2 helpers (sm_103a: FFMA2 reachable only via PTX fma.rn.f32x2)
__device__ __forceinline__ u64 pack2(float v) {
    u64 r; asm("mov.b64 %0, {%1, %1};" : "=l"(r) : "f"(v)); return r;
}
__device__ __forceinline__ void fma2(u64& d, u64 a, u64 b) {
    asm("fma.rn.f32x2 %0, %1, %2, %0;" : "+l"(d) : "l"(a), "l"(b));
}
union F4U { float4 f4; u64 u[2]; float f[4]; };
union H2U { __half2 h2; unsigned int u; };

__device__ __forceinline__ unsigned int h2_bits(__half2 h) {
    H2U x; x.h2 = h; return x.u;
}
__device__ __forceinline__ __half2 bits_h2(unsigned int b) {
    H2U x; x.u = b; return x.h2;
}

__device__ __forceinline__ uint32_t smem_u32(const void* p) {
    uint32_t a;
    asm("{ .reg .u64 t; cvta.to.shared.u64 t, %1; cvt.u32.u64 %0, t; }" : "=r"(a) : "l"(p));
    return a;
}
__device__ __forceinline__ void ldm_x4(uint32_t& r0, uint32_t& r1, uint32_t& r2, uint32_t& r3,
                                       uint32_t addr) {
    asm volatile("ldmatrix.sync.aligned.m8n8.x4.shared.b16 {%0,%1,%2,%3}, [%4];"
                 : "=r"(r0), "=r"(r1), "=r"(r2), "=r"(r3) : "r"(addr));
}
__device__ __forceinline__ void mma_16816(float* c, const uint32_t* a, const uint32_t* b) {
    asm volatile(
        "mma.sync.aligned.m16n8k16.row.col.f32.f16.f16.f32 "
        "{%0,%1,%2,%3}, {%4,%5,%6,%7}, {%8,%9}, {%0,%1,%2,%3};"
        : "+f"(c[0]), "+f"(c[1]), "+f"(c[2]), "+f"(c[3])
        : "r"(a[0]), "r"(a[1]), "r"(a[2]), "r"(a[3]), "r"(b[0]), "r"(b[1]));
}

// packed fp16 tanh (sm_90+): 1 MUFU op for 2 lanes
__device__ __forceinline__ __half2 tanh2(__half2 x) {
    H2U a, b; a.h2 = x;
    asm("tanh.approx.f16x2 %0, %1;" : "=r"(b.u) : "r"(a.u));
    return b.h2;
}
// GeLU (tanh form) in packed fp16: ~8 ops per 2 values
__device__ __forceinline__ __half2 gelu_h2(__half2 x) {
    const __half2 K   = __float2half2_rn(0.044715f);
    const __half2 ONE = __float2half2_rn(1.0f);
    const __half2 C   = __float2half2_rn(0.7978845608028654f);
    const __half2 H   = __float2half2_rn(0.5f);
    __half2 u  = __hmul2(x, x);
    __half2 v  = __hfma2(K, u, ONE);
    __half2 z  = __hmul2(__hmul2(C, x), v);
    __half2 th = tanh2(z);
    return __hmul2(__hmul2(H, x), __hadd2(th, ONE));
}

// ---------------- scratch (__device__ globals; no allocations) ----------------
__device__ __align__(16) __half d_Qh[8 * NPOS * 256]; // [slot][pos][o2] fp16, 39.3 MB
__device__ __align__(16) __half d_featTh[NPOS * 64];  // [pos][c] fp16, 1.2 MB
__device__ __align__(16) __half d_QwTh[8 * 256 * 64]; // [slot][o2][c] fp16, 256 KB
__device__ __align__(16) float d_b1[256];
__device__ __align__(16) float d_C6[256 * 6];         // [o][k]
__device__ __align__(16) float d_bf[256];             // fc1-folded bias
__device__ __align__(16) float d_C6f[6 * 256];        // [k][o2]
__device__ __align__(16) float d_sc3[3 * NPOS];       // skip branch on input grid
// packed geometry: t at [0,12), h at [12,92), w at [92,172)
__device__ __align__(16) float4 d_g4[172];

// =====================================================================
// Launch 1: prep (role blocks)
//   [0,150)   : feat -> feat^T fp16
//   150       : geometry
//   [151,183) : fold_bias (warp per output channel)
//   [183,221) : skip-branch pointwise
//   [221,349) : QwT fold GEMM
// =====================================================================
__global__ void __launch_bounds__(256) k_prep(
    const float* __restrict__ feat,
    const float* __restrict__ dw1_w, const float* __restrict__ dw1_b,
    const float* __restrict__ pw1_w, const float* __restrict__ pw1_b,
    const float* __restrict__ sc_dw_w, const float* __restrict__ sc_dw_b,
    const float* __restrict__ sc_pw_w, const float* __restrict__ sc_pw_b,
    const float* __restrict__ fc1_w)
{
    __shared__ float sbuf[4160];         // aliased per-role
    int b = blockIdx.x;
    int tid = threadIdx.x;

    if (b < 150) {                       // ---- featT fp16 transpose ----
        float* s = sbuf;                 // 64*65
        int p0 = b * 64;
        #pragma unroll
        for (int r = 0; r < 16; r++) {
            int idx = r * 256 + tid;
            int c = idx >> 6, p = idx & 63;
            s[c * 65 + p] = feat[c * NPOS + p0 + p];
        }
        __syncthreads();
        __half2* outp = (__half2*)d_featTh;
        #pragma unroll
        for (int r = 0; r < 8; r++) {
            int idx = r * 256 + tid;
            int p = idx >> 5, cc = idx & 31;
            outp[(p0 + p) * 32 + cc] =
                __floats2half2_rn(s[(2 * cc) * 65 + p], s[(2 * cc + 1) * 65 + p]);
        }
        return;
    }
    if (b == 150) {                      // ---- geometry ----
        int k = tid;
        const int nout[3] = {TOUT, HOUT, WOUT};
        const int nin[3]  = {TIN, HIN, WIN};
        const int off[3]  = {0, 12, 92};
        for (int a = 0; a < 3; a++) {
            if (k >= nout[a]) continue;
            float n_o = (float)nout[a];
            int   ni  = nin[a];
            float n_i = (float)ni;
            float ro = 1.0f / n_o;
            float ri = 1.0f / n_i;
            float c = (-1.0f + ro) + (2.0f * ro) * (float)k;
            float dm = 0.0f, dp = 0.0f;
            int im = 0, ip = 0;
            for (int s = 0; s < 2; s++) {
                float sv = s ? 1.0f : -1.0f;
                float cc = (c + sv * ri) + 1e-6f;
                cc = fminf(fmaxf(cc, -1.0f + 1e-6f), 1.0f - 1e-6f);
                float v = ((cc + 1.0f) * n_i - 1.0f) * 0.5f;
                int idx = (int)rintf(v);               // round half-even == jnp.round
                idx = min(max(idx, 0), ni - 1);
                float l = (-1.0f + ri) + (2.0f * ri) * (float)idx;
                float d = (c - l) * n_i;
                if (s == 0) { im = idx; dm = d; }
                else        { ip = idx; dp = d; }
            }
            float x = ((c + 1.0f) * n_i - 1.0f) * 0.5f;
            x = fminf(fmaxf(x, 0.0f), n_i - 1.0f);
            float x0 = floorf(x);
            int i0 = (int)x0;
            int i1 = min(i0 + 1, ni - 1);
            int pk = im | (ip << 8) | (i0 << 16) | (i1 << 24);
            d_g4[off[a] + k] = make_float4(dm, dp, x - x0, __int_as_float(pk));
        }
        return;
    }
    if (b < 183) {                       // ---- fold_bias: warp per o ----
        int lane = tid & 31;
        int o = (b - 151) * 8 + (tid >> 5);
        const float* row = pw1_w + o * GC;
        float s = 0.0f;
        for (int g = lane; g < GC; g += 32) s += row[g] * dw1_b[g];
        float vc = 0.0f; int bucket = -1;
        if (lane < 24) {
            int i = lane / 3, r = lane % 3;
            vc = row[lane] * dw1_w[lane];
            int st = (i >> 2) & 1, sx = (i >> 1) & 1, sy = i & 1;
            bucket = (r == 0) ? st : (r == 1) ? 2 + sx : 4 + sy;
        }
        float s2 = (lane < 3) ? row[536 + lane] * dw1_w[536 + lane] : 0.0f;
        #pragma unroll
        for (int m = 16; m; m >>= 1) {
            s  += __shfl_xor_sync(0xffffffffu, s,  m);
            s2 += __shfl_xor_sync(0xffffffffu, s2, m);
        }
        #pragma unroll
        for (int k = 0; k < 6; k++) {
            float mval = (bucket == k) ? vc : 0.0f;
            #pragma unroll
            for (int m = 16; m; m >>= 1) mval += __shfl_xor_sync(0xffffffffu, mval, m);
            if (lane == 0) d_C6[o * 6 + k] = mval;
        }
        if (lane == 0) d_b1[o] = pw1_b[o] + s + 2.0f * s2;
        return;
    }
    if (b < 221) {                       // ---- skip branch pointwise ----
        float* shp = sbuf;               // 195
        if (tid < 192) shp[tid] = sc_pw_w[tid] * sc_dw_w[tid & 63];
        if (tid < 3) {
            float bb = sc_pw_b[tid];
            for (int c = 0; c < 64; c++) bb += sc_pw_w[tid * 64 + c] * sc_dw_b[c];
            shp[192 + tid] = bb;
        }
        __syncthreads();
        int pos = (b - 183) * 256 + tid;
        if (pos >= NPOS) return;
        float a0 = shp[192], a1 = shp[193], a2 = shp[194];
        for (int c = 0; c < 64; c++) {
            float v = feat[c * NPOS + pos];
            a0 += shp[c] * v; a1 += shp[64 + c] * v; a2 += shp[128 + c] * v;
        }
        d_sc3[pos] = a0; d_sc3[NPOS + pos] = a1; d_sc3[2 * NPOS + pos] = a2;
        return;
    }
    // ---- QwT fold GEMM: blocks [221,349) ----
    {
        int bb = b - 221;                // 0..127
        float* As  = sbuf;               // 32x33
        float* Bst = sbuf + 1056;        // 32x33
        float* sdw = sbuf + 2112;        // 32
        int ic0 = (bb & 15) * 32;
        int o20 = (bb >> 4) * 32;
        if (tid < 32) sdw[tid] = dw1_w[24 + ic0 + tid];
        __syncthreads();
        float acc[4] = {0, 0, 0, 0};
        int ic_l = tid & 31;
        int o2g  = tid >> 5;
        for (int ko = 0; ko < 256; ko += 32) {
            #pragma unroll
            for (int m = 0; m < 4; m++) {
                int e = m * 256 + tid;
                int o = e >> 5, ic = e & 31;
                As[o * 33 + ic] = pw1_w[(ko + o) * GC + 24 + ic0 + ic] * sdw[ic];
                Bst[o * 33 + ic] = fc1_w[(o20 + o) * 256 + ko + ic];
            }
            __syncthreads();
            #pragma unroll 8
            for (int o = 0; o < 32; o++) {
                float a = As[o * 33 + ic_l];
                #pragma unroll
                for (int j = 0; j < 4; j++)
                    acc[j] += a * Bst[(o2g * 4 + j) * 33 + o];
            }
            __syncthreads();
        }
        int ic = ic0 + ic_l;
        int slot = ic >> 6, c = ic & 63;
        #pragma unroll
        for (int j = 0; j < 4; j++) {
            int o2 = o20 + o2g * 4 + j;
            d_QwTh[(slot * 256 + o2) * 64 + c] = __float2half_rn(acc[j]);
        }
    }
}

// =====================================================================
// Launch 2: phaseA (HMMA) + fold2 rider block
//   blocks [0,1200): Q tiles; epilogue staged through smem for coalesced
//   16B stores. block 1200: fold2 (bf, C6f).
// =====================================================================
__global__ void __launch_bounds__(256) k_phaseA_mma(const float* __restrict__ fc1_w,
                                                    const float* __restrict__ fc1_b) {
    __shared__ __align__(16) char smem_buf[34816];   // 16KB sA | 16KB sB; reused as out tile
    __half* sA = (__half*)smem_buf;
    __half* sB = (__half*)(smem_buf + 16384);
    int tid = threadIdx.x;
    int b = blockIdx.x;

    if (b == 1200) {                     // ---- fold2 rider ----
        float* sb1 = (float*)smem_buf;         // 256
        float* sc6 = (float*)smem_buf + 256;   // 1536
        int o2 = tid;
        sb1[o2] = d_b1[o2];
        for (int idx = o2; idx < 1536; idx += 256) sc6[idx] = d_C6[idx];
        __syncthreads();
        float bf = fc1_b[o2];
        float c6f[6] = {0, 0, 0, 0, 0, 0};
        const float* frow = fc1_w + o2 * 256;
        for (int o = 0; o < 256; o++) {
            float f = frow[o];
            bf += f * sb1[o];
            #pragma unroll
            for (int kk = 0; kk < 6; kk++) c6f[kk] += f * sc6[o * 6 + kk];
        }
        d_bf[o2] = bf;
        #pragma unroll
        for (int kk = 0; kk < 6; kk++) d_C6f[kk * 256 + o2] = c6f[kk];
        return;
    }

    int lane = tid & 31;
    int wid = tid >> 5;
    int p_tile = b % 75;
    int n_half = (b / 75) & 1;
    int slot = b / 150;
    int p0 = p_tile * 128;
    int n0 = n_half * 128;

    const uint4* gA = (const uint4*)(d_featTh + (size_t)p0 * 64);
    const uint4* gB = (const uint4*)(d_QwTh + (size_t)(slot * 256 + n0) * 64);
    #pragma unroll
    for (int r = 0; r < 4; r++) {
        int idx = r * 256 + tid;
        int row = idx >> 3, ck = idx & 7;
        int sck = ck ^ (row & 7);
        *(uint4*)&sA[row * 64 + sck * 8] = gA[idx];
        *(uint4*)&sB[row * 64 + sck * 8] = gB[idx];
    }
    __syncthreads();

    int wm = (wid & 3) * 32;
    int wn = (wid >> 2) * 64;
    uint32_t baseA = smem_u32(sA);
    uint32_t baseB = smem_u32(sB);

    float acc[2][8][4];
    #pragma unroll
    for (int mi = 0; mi < 2; mi++)
        #pragma unroll
        for (int j = 0; j < 8; j++)
            #pragma unroll
            for (int q = 0; q < 4; q++) acc[mi][j][q] = 0.0f;

    #pragma unroll
    for (int ks = 0; ks < 4; ks++) {
        int kc = ks * 2;
        uint32_t a[2][4];
        #pragma unroll
        for (int mi = 0; mi < 2; mi++) {
            int row = wm + mi * 16 + (lane & 15);
            int ck = (kc + (lane >> 4)) ^ (row & 7);
            ldm_x4(a[mi][0], a[mi][1], a[mi][2], a[mi][3],
                   baseA + (uint32_t)(row * 64 + ck * 8) * 2);
        }
        uint32_t bfr[8][2];
        #pragma unroll
        for (int jp = 0; jp < 4; jp++) {
            int row = wn + jp * 16 + ((lane >> 4) & 1) * 8 + (lane & 7);
            int ck = (kc + ((lane >> 3) & 1)) ^ (row & 7);
            ldm_x4(bfr[2 * jp][0], bfr[2 * jp][1], bfr[2 * jp + 1][0], bfr[2 * jp + 1][1],
                   baseB + (uint32_t)(row * 64 + ck * 8) * 2);
        }
        #pragma unroll
        for (int mi = 0; mi < 2; mi++)
            #pragma unroll
            for (int j = 0; j < 8; j++)
                mma_16816(acc[mi][j], a[mi], bfr[j]);
    }

    // ---- epilogue: fragments -> padded smem tile, then coalesced 16B stores ----
    __syncthreads();
    __half2* sOut = (__half2*)smem_buf;            // row stride 68 half2 (136 halves)
    #pragma unroll
    for (int mi = 0; mi < 2; mi++) {
        int r0 = wm + mi * 16 + (lane >> 2);
        int c2 = (wn >> 1) + (lane & 3);
        #pragma unroll
        for (int j = 0; j < 8; j++) {
            sOut[r0 * 68 + c2 + j * 4]       = __floats2half2_rn(acc[mi][j][0], acc[mi][j][1]);
            sOut[(r0 + 8) * 68 + c2 + j * 4] = __floats2half2_rn(acc[mi][j][2], acc[mi][j][3]);
        }
    }
    __syncthreads();
    const __half* sH = (const __half*)smem_buf;
    #pragma unroll
    for (int it = 0; it < 8; it++) {
        int idx = it * 256 + tid;
        int row = idx >> 4, u4 = idx & 15;
        uint4 v = *(const uint4*)(sH + row * 136 + u4 * 8);
        *(uint4*)(d_Qh + (((size_t)(slot * NPOS + p0 + row)) << 8) + n0 + u4 * 8) = v;
    }
}

// =====================================================================
// combine (R9/R12 version — best measured): warp-persistent, constants in
// registers, fp32 fma2 prologue overlapping fp16 gather chain, h2 GeLU,
// split reduction. Do NOT trade these registers for occupancy — measured
// worse twice (R10, R13/14).
// =====================================================================
__global__ void __launch_bounds__(256) k_combine(const float* __restrict__ fc2_w,
                                                 const float* __restrict__ fc2_b,
                                                 float* __restrict__ out) {
    int lane = threadIdx.x & 31;
    int W = blockIdx.x * 8 + (threadIdx.x >> 5);     // 0..4799
    int t = W / 400;
    int rem = W - t * 400;
    int h = rem / 5;
    int w0 = (rem - h * 5) * 16;
    int ch = lane * 8;

    F4U bf0, bf1;
    bf0.f4 = *(const float4*)&d_bf[ch];
    bf1.f4 = *(const float4*)&d_bf[ch + 4];
    F4U c6a[6], c6b[6];
    #pragma unroll
    for (int kk = 0; kk < 6; kk++) {
        c6a[kk].f4 = *(const float4*)&d_C6f[kk * 256 + ch];
        c6b[kk].f4 = *(const float4*)&d_C6f[kk * 256 + ch + 4];
    }
    float4 f2a[3], f2b[3];
    #pragma unroll
    for (int kk = 0; kk < 3; kk++) {
        f2a[kk] = *(const float4*)&fc2_w[kk * 256 + ch];
        f2b[kk] = *(const float4*)&fc2_w[kk * 256 + ch + 4];
    }
    float obl = 0.0f;
    if (lane == 0)       obl = fc2_b[0];
    else if (lane == 8)  obl = fc2_b[1];
    else if (lane == 16) obl = fc2_b[2];

    float4 gt = d_g4[t];
    float4 gh = d_g4[12 + h];
    int pkt = __float_as_int(gt.w);
    int pkh = __float_as_int(gh.w);
    int it0 = pkt & 255, it1 = (pkt >> 8) & 255, lt0 = (pkt >> 16) & 255, lt1 = (pkt >> 24) & 255;
    int ih0 = pkh & 255, ih1 = (pkh >> 8) & 255, lh0 = (pkh >> 16) & 255, lh1 = (pkh >> 24) & 255;
    float dtm = gt.x, dtp = gt.y, ft = gt.z;
    float dhm = gh.x, dhp = gh.y, fh = gh.z;
    float at0 = fabsf(dtm), at1 = fabsf(dtp);
    float ah0 = fabsf(dhm), ah1 = fabsf(dhp);
    float atah[4] = {at0 * ah0, at0 * ah1, at1 * ah0, at1 * ah1};
    int bth[4] = {(it0 * HIN + ih0) * WIN, (it0 * HIN + ih1) * WIN,
                  (it1 * HIN + ih0) * WIN, (it1 * HIN + ih1) * WIN};

    F4U P0 = bf0, P1 = bf1;
    {
        u64 a = pack2(dtm), b = pack2(dtp), c = pack2(dhm), d = pack2(dhp);
        fma2(P0.u[0], a, c6a[0].u[0]); fma2(P0.u[1], a, c6a[0].u[1]);
        fma2(P1.u[0], a, c6b[0].u[0]); fma2(P1.u[1], a, c6b[0].u[1]);
        fma2(P0.u[0], b, c6a[1].u[0]); fma2(P0.u[1], b, c6a[1].u[1]);
        fma2(P1.u[0], b, c6b[1].u[0]); fma2(P1.u[1], b, c6b[1].u[1]);
        fma2(P0.u[0], c, c6a[2].u[0]); fma2(P0.u[1], c, c6a[2].u[1]);
        fma2(P1.u[0], c, c6b[2].u[0]); fma2(P1.u[1], c, c6b[2].u[1]);
        fma2(P0.u[0], d, c6a[3].u[0]); fma2(P0.u[1], d, c6a[3].u[1]);
        fma2(P1.u[0], d, c6b[3].u[0]); fma2(P1.u[1], d, c6b[3].u[1]);
    }

    int jt = (lane >> 2) & 1, jh = (lane >> 1) & 1, jw = lane & 1;
    int p_th = ((jt ? lt1 : lt0) * HIN + (jh ? lh1 : lh0)) * WIN;
    float wt_th = (jt ? ft : 1.0f - ft) * (jh ? fh : 1.0f - fh);

    int vbase = (t * HOUT + h) * WOUT + w0;

    for (int k = 0; k < 16; k++) {
        int w = w0 + k;
        float4 gw = d_g4[92 + w];
        int pkw = __float_as_int(gw.w);
        int iw0 = pkw & 255, iw1 = (pkw >> 8) & 255;
        int lw0 = (pkw >> 16) & 255, lw1 = (pkw >> 24) & 255;
        float dwm = gw.x, dwp = gw.y, fw = gw.z;
        float aw0f = fabsf(dwm), aw1f = fabsf(dwp);

        float area[8]; int pos[8]; float tot = 0.0f;
        #pragma unroll
        for (int i = 0; i < 8; i++) {
            float aa = atah[i >> 1] * ((i & 1) ? aw1f : aw0f) + 1e-9f;
            area[i] = aa; tot += aa;
            pos[i] = bth[i >> 1] + ((i & 1) ? iw1 : iw0);
        }
        float rtot = 1.0f / tot;

        F4U A0 = P0, A1 = P1;
        {
            u64 am = pack2(dwm), ap = pack2(dwp);
            fma2(A0.u[0], am, c6a[4].u[0]); fma2(A0.u[1], am, c6a[4].u[1]);
            fma2(A1.u[0], am, c6b[4].u[0]); fma2(A1.u[1], am, c6b[4].u[1]);
            fma2(A0.u[0], ap, c6a[5].u[0]); fma2(A0.u[1], ap, c6a[5].u[1]);
            fma2(A1.u[0], ap, c6b[5].u[0]); fma2(A1.u[1], ap, c6b[5].u[1]);
        }

        __half2 hacc0 = __float2half2_rn(0.0f), hacc1 = hacc0, hacc2 = hacc0, hacc3 = hacc0;
        #pragma unroll
        for (int i = 0; i < 8; i++) {
            __half2 wp = __float2half2_rn(area[7 - i]);
            uint4 qv = *(const uint4*)(d_Qh + ((size_t)(i * NPOS + pos[i]) << 8) + ch);
            hacc0 = __hfma2(bits_h2(qv.x), wp, hacc0);
            hacc1 = __hfma2(bits_h2(qv.y), wp, hacc1);
            hacc2 = __hfma2(bits_h2(qv.z), wp, hacc2);
            hacc3 = __hfma2(bits_h2(qv.w), wp, hacc3);
        }
        float2 qf0 = __half22float2(hacc0);
        float2 qf1 = __half22float2(hacc1);
        float2 qf2 = __half22float2(hacc2);
        float2 qf3 = __half22float2(hacc3);
        __half2 xh0 = __floats2half2_rn(fmaf(qf0.x, rtot, A0.f[0]), fmaf(qf0.y, rtot, A0.f[1]));
        __half2 xh1 = __floats2half2_rn(fmaf(qf1.x, rtot, A0.f[2]), fmaf(qf1.y, rtot, A0.f[3]));
        __half2 xh2 = __floats2half2_rn(fmaf(qf2.x, rtot, A1.f[0]), fmaf(qf2.y, rtot, A1.f[1]));
        __half2 xh3 = __floats2half2_rn(fmaf(qf3.x, rtot, A1.f[2]), fmaf(qf3.y, rtot, A1.f[3]));
        float2 g0 = __half22float2(gelu_h2(xh0));
        float2 g1 = __half22float2(gelu_h2(xh1));
        float2 g2 = __half22float2(gelu_h2(xh2));
        float2 g3 = __half22float2(gelu_h2(xh3));

        float s0 = f2a[0].x * g0.x + f2a[0].y * g0.y + f2a[0].z * g1.x + f2a[0].w * g1.y
                 + f2b[0].x * g2.x + f2b[0].y * g2.y + f2b[0].z * g3.x + f2b[0].w * g3.y;
        float s1 = f2a[1].x * g0.x + f2a[1].y * g0.y + f2a[1].z * g1.x + f2a[1].w * g1.y
                 + f2b[1].x * g2.x + f2b[1].y * g2.y + f2b[1].z * g3.x + f2b[1].w * g3.y;
        float s2 = f2a[2].x * g0.x + f2a[2].y * g0.y + f2a[2].z * g1.x + f2a[2].w * g1.y
                 + f2b[2].x * g2.x + f2b[2].y * g2.y + f2b[2].z * g3.x + f2b[2].w * g3.y;

        if (lane < 8) {
            float wt = wt_th * (jw ? fw : 1.0f - fw);
            int p = p_th + (jw ? lw1 : lw0);
            s0 += wt * d_sc3[p];
            s1 += wt * d_sc3[NPOS + p];
            s2 += wt * d_sc3[2 * NPOS + p];
        }
        s0 += __shfl_xor_sync(0xffffffffu, s0, 16);
        s1 += __shfl_xor_sync(0xffffffffu, s1, 16);
        s2 += __shfl_xor_sync(0xffffffffu, s2, 16);
        s0 += __shfl_xor_sync(0xffffffffu, s0, 8);
        s1 += __shfl_xor_sync(0xffffffffu, s1, 8);
        s2 += __shfl_xor_sync(0xffffffffu, s2, 8);
        float v = (lane < 8) ? s0 : ((lane < 16) ? s1 : s2);
        v += __shfl_xor_sync(0xffffffffu, v, 4);
        v += __shfl_xor_sync(0xffffffffu, v, 2);
        v += __shfl_xor_sync(0xffffffffu, v, 1);
        if ((lane & 7) == 0 && lane < 24) {
            out[(lane >> 3) * NVOX + vbase + k] = v + obl;
        }
    }
}

extern "C" void kernel_launch(void* const* d_in, const int* in_sizes, int n_in,
                              void* d_out, int out_size) {
    const float* feat    = (const float*)d_in[0];
    const float* dw1_w   = (const float*)d_in[1];
    const float* dw1_b   = (const float*)d_in[2];
    const float* pw1_w   = (const float*)d_in[3];
    const float* pw1_b   = (const float*)d_in[4];
    const float* fc1_w   = (const float*)d_in[5];
    const float* fc1_b   = (const float*)d_in[6];
    const float* fc2_w   = (const float*)d_in[7];
    const float* fc2_b   = (const float*)d_in[8];
    const float* sc_dw_w = (const float*)d_in[9];
    const float* sc_dw_b = (const float*)d_in[10];
    const float* sc_pw_w = (const float*)d_in[11];
    const float* sc_pw_b = (const float*)d_in[12];
    float* out = (float*)d_out;

    k_prep<<<349, 256>>>(feat, dw1_w, dw1_b, pw1_w, pw1_b,
                         sc_dw_w, sc_dw_b, sc_pw_w, sc_pw_b, fc1_w);
    k_phaseA_mma<<<1201, 256>>>(fc1_w, fc1_b);
    k_combine<<<600, 256>>>(fc2_w, fc2_b, out);
}

// round 16
// speedup vs baseline: 1.8818x; 1.0270x over previous
#include <cuda_runtime.h>
#include <cuda_fp16.h>
#include <math.h>
#include <stdint.h>

#define TIN 6
#define HIN 40
#define WIN 40
#define TOUT 12
#define HOUT 80
#define WOUT 80
#define NPOS 9600    // 6*40*40
#define NVOX 76800   // 12*80*80
#define GC 539

typedef unsigned long long u64;

// packed fp32x2 helpers (sm_103a: FFMA2 reachable only via PTX fma.rn.f32x2)
__device__ __forceinline__ u64 pack2(float v) {
    u64 r; asm("mov.b64 %0, {%1, %1};" : "=l"(r) : "f"(v)); return r;
}
__device__ __forceinline__ void fma2(u64& d, u64 a, u64 b) {
    asm("fma.rn.f32x2 %0, %1, %2, %0;" : "+l"(d) : "l"(a), "l"(b));
}
union F4U { float4 f4; u64 u[2]; float f[4]; };
union H2U { __half2 h2; unsigned int u; };

__device__ __forceinline__ unsigned int h2_bits(__half2 h) {
    H2U x; x.h2 = h; return x.u;
}
__device__ __forceinline__ __half2 bits_h2(unsigned int b) {
    H2U x; x.u = b; return x.h2;
}

__device__ __forceinline__ uint32_t smem_u32(const void* p) {
    uint32_t a;
    asm("{ .reg .u64 t; cvta.to.shared.u64 t, %1; cvt.u32.u64 %0, t; }" : "=r"(a) : "l"(p));
    return a;
}
__device__ __forceinline__ void ldm_x4(uint32_t& r0, uint32_t& r1, uint32_t& r2, uint32_t& r3,
                                       uint32_t addr) {
    asm volatile("ldmatrix.sync.aligned.m8n8.x4.shared.b16 {%0,%1,%2,%3}, [%4];"
                 : "=r"(r0), "=r"(r1), "=r"(r2), "=r"(r3) : "r"(addr));
}
__device__ __forceinline__ void mma_16816(float* c, const uint32_t* a, const uint32_t* b) {
    asm volatile(
        "mma.sync.aligned.m16n8k16.row.col.f32.f16.f16.f32 "
        "{%0,%1,%2,%3}, {%4,%5,%6,%7}, {%8,%9}, {%0,%1,%2,%3};"
        : "+f"(c[0]), "+f"(c[1]), "+f"(c[2]), "+f"(c[3])
        : "r"(a[0]), "r"(a[1]), "r"(a[2]), "r"(a[3]), "r"(b[0]), "r"(b[1]));
}

// packed fp16 tanh (sm_90+): 1 MUFU op for 2 lanes
__device__ __forceinline__ __half2 tanh2(__half2 x) {
    H2U a, b; a.h2 = x;
    asm("tanh.approx.f16x2 %0, %1;" : "=r"(b.u) : "r"(a.u));
    return b.h2;
}
// GeLU (tanh form) in packed fp16
__device__ __forceinline__ __half2 gelu_h2(__half2 x) {
    const __half2 K   = __float2half2_rn(0.044715f);
    const __half2 ONE = __float2half2_rn(1.0f);
    const __half2 C   = __float2half2_rn(0.7978845608028654f);
    const __half2 H   = __float2half2_rn(0.5f);
    __half2 u  = __hmul2(x, x);
    __half2 v  = __hfma2(K, u, ONE);
    __half2 z  = __hmul2(__hmul2(C, x), v);
    __half2 th = tanh2(z);
    return __hmul2(__hmul2(H, x), __hadd2(th, ONE));
}

// ---------------- scratch (__device__ globals; no allocations) ----------------
__device__ __align__(16) __half d_Qh[8 * NPOS * 256]; // [slot][pos][o2] fp16, 39.3 MB
__device__ __align__(16) __half d_featTh[NPOS * 64];  // [pos][c] fp16, 1.2 MB
__device__ __align__(16) __half d_QwTh[8 * 256 * 64]; // [slot][o2][c] fp16, 256 KB
__device__ __align__(16) float d_b1[256];
__device__ __align__(16) float d_C6[256 * 6];         // [o][k]
__device__ __align__(16) float d_bf[256];             // fc1-folded bias
__device__ __align__(16) float d_C6f[6 * 256];        // [k][o2]
__device__ __align__(16) float d_sc3[3 * NPOS];       // skip branch on input grid
// packed geometry: t at [0,12), h at [12,92), w at [92,172)
__device__ __align__(16) float4 d_g4[172];

// =====================================================================
// Launch 1: prep (role blocks)
//   [0,150)   : feat -> feat^T fp16
//   [150,182) : fold_bias (warp per output channel)
//   [182,310) : QwT fold GEMM (register double-buffered)
//   (geometry + skip-pointwise moved to phaseA riders)
// =====================================================================
__global__ void __launch_bounds__(256) k_prep(
    const float* __restrict__ feat,
    const float* __restrict__ dw1_w, const float* __restrict__ dw1_b,
    const float* __restrict__ pw1_w, const float* __restrict__ pw1_b,
    const float* __restrict__ fc1_w)
{
    __shared__ float sbuf[4160];         // aliased per-role
    int b = blockIdx.x;
    int tid = threadIdx.x;

    if (b < 150) {                       // ---- featT fp16 transpose ----
        float* s = sbuf;                 // 64*65
        int p0 = b * 64;
        #pragma unroll
        for (int r = 0; r < 16; r++) {
            int idx = r * 256 + tid;
            int c = idx >> 6, p = idx & 63;
            s[c * 65 + p] = feat[c * NPOS + p0 + p];
        }
        __syncthreads();
        __half2* outp = (__half2*)d_featTh;
        #pragma unroll
        for (int r = 0; r < 8; r++) {
            int idx = r * 256 + tid;
            int p = idx >> 5, cc = idx & 31;
            outp[(p0 + p) * 32 + cc] =
                __floats2half2_rn(s[(2 * cc) * 65 + p], s[(2 * cc + 1) * 65 + p]);
        }
        return;
    }
    if (b < 182) {                       // ---- fold_bias: warp per o ----
        int lane = tid & 31;
        int o = (b - 150) * 8 + (tid >> 5);
        const float* row = pw1_w + o * GC;
        float s = 0.0f;
        for (int g = lane; g < GC; g += 32) s += row[g] * dw1_b[g];
        float vc = 0.0f; int bucket = -1;
        if (lane < 24) {
            int i = lane / 3, r = lane % 3;
            vc = row[lane] * dw1_w[lane];
            int st = (i >> 2) & 1, sx = (i >> 1) & 1, sy = i & 1;
            bucket = (r == 0) ? st : (r == 1) ? 2 + sx : 4 + sy;
        }
        float s2 = (lane < 3) ? row[536 + lane] * dw1_w[536 + lane] : 0.0f;
        #pragma unroll
        for (int m = 16; m; m >>= 1) {
            s  += __shfl_xor_sync(0xffffffffu, s,  m);
            s2 += __shfl_xor_sync(0xffffffffu, s2, m);
        }
        #pragma unroll
        for (int k = 0; k < 6; k++) {
            float mval = (bucket == k) ? vc : 0.0f;
            #pragma unroll
            for (int m = 16; m; m >>= 1) mval += __shfl_xor_sync(0xffffffffu, mval, m);
            if (lane == 0) d_C6[o * 6 + k] = mval;
        }
        if (lane == 0) d_b1[o] = pw1_b[o] + s + 2.0f * s2;
        return;
    }
    // ---- QwT fold GEMM: blocks [182,310), register double-buffered ----
    {
        int bb = b - 182;                // 0..127
        float* As  = sbuf;               // 32x33
        float* Bst = sbuf + 1056;        // 32x33
        float* sdw = sbuf + 2112;        // 32
        int ic0 = (bb & 15) * 32;
        int o20 = (bb >> 4) * 32;
        if (tid < 32) sdw[tid] = dw1_w[24 + ic0 + tid];
        __syncthreads();
        int ic_l = tid & 31;
        int o2g  = tid >> 5;
        int eo[4], eic[4];
        #pragma unroll
        for (int m = 0; m < 4; m++) {
            int e = m * 256 + tid;
            eo[m] = e >> 5; eic[m] = e & 31;
        }
        float ra[4], rb[4];
        #pragma unroll
        for (int m = 0; m < 4; m++) {
            ra[m] = pw1_w[eo[m] * GC + 24 + ic0 + eic[m]] * sdw[eic[m]];
            rb[m] = fc1_w[(o20 + eo[m]) * 256 + eic[m]];
        }
        float acc[4] = {0, 0, 0, 0};
        for (int ko = 0; ko < 256; ko += 32) {
            #pragma unroll
            for (int m = 0; m < 4; m++) {
                As[eo[m] * 33 + eic[m]]  = ra[m];
                Bst[eo[m] * 33 + eic[m]] = rb[m];
            }
            __syncthreads();
            if (ko + 32 < 256) {         // prefetch next tile (hides DRAM latency)
                #pragma unroll
                for (int m = 0; m < 4; m++) {
                    ra[m] = pw1_w[(ko + 32 + eo[m]) * GC + 24 + ic0 + eic[m]] * sdw[eic[m]];
                    rb[m] = fc1_w[(o20 + eo[m]) * 256 + ko + 32 + eic[m]];
                }
            }
            #pragma unroll 8
            for (int o = 0; o < 32; o++) {
                float a = As[o * 33 + ic_l];
                #pragma unroll
                for (int j = 0; j < 4; j++)
                    acc[j] += a * Bst[(o2g * 4 + j) * 33 + o];
            }
            __syncthreads();
        }
        int ic = ic0 + ic_l;
        int slot = ic >> 6, c = ic & 63;
        #pragma unroll
        for (int j = 0; j < 4; j++) {
            int o2 = o20 + o2g * 4 + j;
            d_QwTh[(slot * 256 + o2) * 64 + c] = __float2half_rn(acc[j]);
        }
    }
}

// =====================================================================
// Launch 2: phaseA (HMMA) + rider blocks
//   [0,1200)    : Q tiles (smem-staged coalesced epilogue)
//   1200        : fold2 (bf, C6f) — needs prep's d_b1/d_C6
//   1201        : geometry
//   [1202,1240) : skip-branch pointwise
// =====================================================================
__global__ void __launch_bounds__(256) k_phaseA_mma(
    const float* __restrict__ fc1_w, const float* __restrict__ fc1_b,
    const float* __restrict__ feat,
    const float* __restrict__ sc_dw_w, const float* __restrict__ sc_dw_b,
    const float* __restrict__ sc_pw_w, const float* __restrict__ sc_pw_b)
{
    __shared__ __align__(16) char smem_buf[34816];   // 16KB sA | 16KB sB; reused as out tile
    __half* sA = (__half*)smem_buf;
    __half* sB = (__half*)(smem_buf + 16384);
    int tid = threadIdx.x;
    int b = blockIdx.x;

    if (b >= 1200) {
        int rb = b - 1200;
        if (rb == 0) {                   // ---- fold2 rider ----
            float* sb1 = (float*)smem_buf;         // 256
            float* sc6 = (float*)smem_buf + 256;   // 1536
            int o2 = tid;
            sb1[o2] = d_b1[o2];
            for (int idx = o2; idx < 1536; idx += 256) sc6[idx] = d_C6[idx];
            __syncthreads();
            float bf = fc1_b[o2];
            float c6f[6] = {0, 0, 0, 0, 0, 0};
            const float* frow = fc1_w + o2 * 256;
            for (int o = 0; o < 256; o++) {
                float f = frow[o];
                bf += f * sb1[o];
                #pragma unroll
                for (int kk = 0; kk < 6; kk++) c6f[kk] += f * sc6[o * 6 + kk];
            }
            d_bf[o2] = bf;
            #pragma unroll
            for (int kk = 0; kk < 6; kk++) d_C6f[kk * 256 + o2] = c6f[kk];
            return;
        }
        if (rb == 1) {                   // ---- geometry rider ----
            int k = tid;
            const int nout[3] = {TOUT, HOUT, WOUT};
            const int nin[3]  = {TIN, HIN, WIN};
            const int off[3]  = {0, 12, 92};
            for (int a = 0; a < 3; a++) {
                if (k >= nout[a]) continue;
                float n_o = (float)nout[a];
                int   ni  = nin[a];
                float n_i = (float)ni;
                float ro = 1.0f / n_o;
                float ri = 1.0f / n_i;
                float c = (-1.0f + ro) + (2.0f * ro) * (float)k;
                float dm = 0.0f, dp = 0.0f;
                int im = 0, ip = 0;
                for (int s = 0; s < 2; s++) {
                    float sv = s ? 1.0f : -1.0f;
                    float cc = (c + sv * ri) + 1e-6f;
                    cc = fminf(fmaxf(cc, -1.0f + 1e-6f), 1.0f - 1e-6f);
                    float v = ((cc + 1.0f) * n_i - 1.0f) * 0.5f;
                    int idx = (int)rintf(v);           // round half-even == jnp.round
                    idx = min(max(idx, 0), ni - 1);
                    float l = (-1.0f + ri) + (2.0f * ri) * (float)idx;
                    float d = (c - l) * n_i;
                    if (s == 0) { im = idx; dm = d; }
                    else        { ip = idx; dp = d; }
                }
                float x = ((c + 1.0f) * n_i - 1.0f) * 0.5f;
                x = fminf(fmaxf(x, 0.0f), n_i - 1.0f);
                float x0 = floorf(x);
                int i0 = (int)x0;
                int i1 = min(i0 + 1, ni - 1);
                int pk = im | (ip << 8) | (i0 << 16) | (i1 << 24);
                d_g4[off[a] + k] = make_float4(dm, dp, x - x0, __int_as_float(pk));
            }
            return;
        }
        // ---- skip-branch pointwise rider: rb in [2,40) ----
        {
            float* shp = (float*)smem_buf;   // 195
            if (tid < 192) shp[tid] = sc_pw_w[tid] * sc_dw_w[tid & 63];
            if (tid < 3) {
                float bb = sc_pw_b[tid];
                for (int c = 0; c < 64; c++) bb += sc_pw_w[tid * 64 + c] * sc_dw_b[c];
                shp[192 + tid] = bb;
            }
            __syncthreads();
            int pos = (rb - 2) * 256 + tid;
            if (pos >= NPOS) return;
            float a0 = shp[192], a1 = shp[193], a2 = shp[194];
            for (int c = 0; c < 64; c++) {
                float v = feat[c * NPOS + pos];
                a0 += shp[c] * v; a1 += shp[64 + c] * v; a2 += shp[128 + c] * v;
            }
            d_sc3[pos] = a0; d_sc3[NPOS + pos] = a1; d_sc3[2 * NPOS + pos] = a2;
            return;
        }
    }

    int lane = tid & 31;
    int wid = tid >> 5;
    int p_tile = b % 75;
    int n_half = (b / 75) & 1;
    int slot = b / 150;
    int p0 = p_tile * 128;
    int n0 = n_half * 128;

    const uint4* gA = (const uint4*)(d_featTh + (size_t)p0 * 64);
    const uint4* gB = (const uint4*)(d_QwTh + (size_t)(slot * 256 + n0) * 64);
    #pragma unroll
    for (int r = 0; r < 4; r++) {
        int idx = r * 256 + tid;
        int row = idx >> 3, ck = idx & 7;
        int sck = ck ^ (row & 7);
        *(uint4*)&sA[row * 64 + sck * 8] = gA[idx];
        *(uint4*)&sB[row * 64 + sck * 8] = gB[idx];
    }
    __syncthreads();

    int wm = (wid & 3) * 32;
    int wn = (wid >> 2) * 64;
    uint32_t baseA = smem_u32(sA);
    uint32_t baseB = smem_u32(sB);

    float acc[2][8][4];
    #pragma unroll
    for (int mi = 0; mi < 2; mi++)
        #pragma unroll
        for (int j = 0; j < 8; j++)
            #pragma unroll
            for (int q = 0; q < 4; q++) acc[mi][j][q] = 0.0f;

    #pragma unroll
    for (int ks = 0; ks < 4; ks++) {
        int kc = ks * 2;
        uint32_t a[2][4];
        #pragma unroll
        for (int mi = 0; mi < 2; mi++) {
            int row = wm + mi * 16 + (lane & 15);
            int ck = (kc + (lane >> 4)) ^ (row & 7);
            ldm_x4(a[mi][0], a[mi][1], a[mi][2], a[mi][3],
                   baseA + (uint32_t)(row * 64 + ck * 8) * 2);
        }
        uint32_t bfr[8][2];
        #pragma unroll
        for (int jp = 0; jp < 4; jp++) {
            int row = wn + jp * 16 + ((lane >> 4) & 1) * 8 + (lane & 7);
            int ck = (kc + ((lane >> 3) & 1)) ^ (row & 7);
            ldm_x4(bfr[2 * jp][0], bfr[2 * jp][1], bfr[2 * jp + 1][0], bfr[2 * jp + 1][1],
                   baseB + (uint32_t)(row * 64 + ck * 8) * 2);
        }
        #pragma unroll
        for (int mi = 0; mi < 2; mi++)
            #pragma unroll
            for (int j = 0; j < 8; j++)
                mma_16816(acc[mi][j], a[mi], bfr[j]);
    }

    // ---- epilogue: fragments -> padded smem tile, then coalesced 16B stores ----
    __syncthreads();
    __half2* sOut = (__half2*)smem_buf;            // row stride 68 half2 (136 halves)
    #pragma unroll
    for (int mi = 0; mi < 2; mi++) {
        int r0 = wm + mi * 16 + (lane >> 2);
        int c2 = (wn >> 1) + (lane & 3);
        #pragma unroll
        for (int j = 0; j < 8; j++) {
            sOut[r0 * 68 + c2 + j * 4]       = __floats2half2_rn(acc[mi][j][0], acc[mi][j][1]);
            sOut[(r0 + 8) * 68 + c2 + j * 4] = __floats2half2_rn(acc[mi][j][2], acc[mi][j][3]);
        }
    }
    __syncthreads();
    const __half* sH = (const __half*)smem_buf;
    #pragma unroll
    for (int it = 0; it < 8; it++) {
        int idx = it * 256 + tid;
        int row = idx >> 4, u4 = idx & 15;
        uint4 v = *(const uint4*)(sH + row * 136 + u4 * 8);
        *(uint4*)(d_Qh + (((size_t)(slot * NPOS + p0 + row)) << 8) + n0 + u4 * 8) = v;
    }
}

// =====================================================================
// combine (best measured): warp-persistent, constants in registers,
// fp32 fma2 prologue overlapping fp16 gather chain, h2 GeLU, split
// reduction. Do NOT trade these registers for occupancy — measured worse
// twice (R10, R13/14).
// =====================================================================
__global__ void __launch_bounds__(256) k_combine(const float* __restrict__ fc2_w,
                                                 const float* __restrict__ fc2_b,
                                                 float* __restrict__ out) {
    int lane = threadIdx.x & 31;
    int W = blockIdx.x * 8 + (threadIdx.x >> 5);     // 0..4799
    int t = W / 400;
    int rem = W - t * 400;
    int h = rem / 5;
    int w0 = (rem - h * 5) * 16;
    int ch = lane * 8;

    F4U bf0, bf1;
    bf0.f4 = *(const float4*)&d_bf[ch];
    bf1.f4 = *(const float4*)&d_bf[ch + 4];
    F4U c6a[6], c6b[6];
    #pragma unroll
    for (int kk = 0; kk < 6; kk++) {
        c6a[kk].f4 = *(const float4*)&d_C6f[kk * 256 + ch];
        c6b[kk].f4 = *(const float4*)&d_C6f[kk * 256 + ch + 4];
    }
    float4 f2a[3], f2b[3];
    #pragma unroll
    for (int kk = 0; kk < 3; kk++) {
        f2a[kk] = *(const float4*)&fc2_w[kk * 256 + ch];
        f2b[kk] = *(const float4*)&fc2_w[kk * 256 + ch + 4];
    }
    float obl = 0.0f;
    if (lane == 0)       obl = fc2_b[0];
    else if (lane == 8)  obl = fc2_b[1];
    else if (lane == 16) obl = fc2_b[2];

    float4 gt = d_g4[t];
    float4 gh = d_g4[12 + h];
    int pkt = __float_as_int(gt.w);
    int pkh = __float_as_int(gh.w);
    int it0 = pkt & 255, it1 = (pkt >> 8) & 255, lt0 = (pkt >> 16) & 255, lt1 = (pkt >> 24) & 255;
    int ih0 = pkh & 255, ih1 = (pkh >> 8) & 255, lh0 = (pkh >> 16) & 255, lh1 = (pkh >> 24) & 255;
    float dtm = gt.x, dtp = gt.y, ft = gt.z;
    float dhm = gh.x, dhp = gh.y, fh = gh.z;
    float at0 = fabsf(dtm), at1 = fabsf(dtp);
    float ah0 = fabsf(dhm), ah1 = fabsf(dhp);
    float atah[4] = {at0 * ah0, at0 * ah1, at1 * ah0, at1 * ah1};
    int bth[4] = {(it0 * HIN + ih0) * WIN, (it0 * HIN + ih1) * WIN,
                  (it1 * HIN + ih0) * WIN, (it1 * HIN + ih1) * WIN};

    F4U P0 = bf0, P1 = bf1;
    {
        u64 a = pack2(dtm), b = pack2(dtp), c = pack2(dhm), d = pack2(dhp);
        fma2(P0.u[0], a, c6a[0].u[0]); fma2(P0.u[1], a, c6a[0].u[1]);
        fma2(P1.u[0], a, c6b[0].u[0]); fma2(P1.u[1], a, c6b[0].u[1]);
        fma2(P0.u[0], b, c6a[1].u[0]); fma2(P0.u[1], b, c6a[1].u[1]);
        fma2(P1.u[0], b, c6b[1].u[0]); fma2(P1.u[1], b, c6b[1].u[1]);
        fma2(P0.u[0], c, c6a[2].u[0]); fma2(P0.u[1], c, c6a[2].u[1]);
        fma2(P1.u[0], c, c6b[2].u[0]); fma2(P1.u[1], c, c6b[2].u[1]);
        fma2(P0.u[0], d, c6a[3].u[0]); fma2(P0.u[1], d, c6a[3].u[1]);
        fma2(P1.u[0], d, c6b[3].u[0]); fma2(P1.u[1], d, c6b[3].u[1]);
    }

    int jt = (lane >> 2) & 1, jh = (lane >> 1) & 1, jw = lane & 1;
    int p_th = ((jt ? lt1 : lt0) * HIN + (jh ? lh1 : lh0)) * WIN;
    float wt_th = (jt ? ft : 1.0f - ft) * (jh ? fh : 1.0f - fh);

    int vbase = (t * HOUT + h) * WOUT + w0;

    for (int k = 0; k < 16; k++) {
        int w = w0 + k;
        float4 gw = d_g4[92 + w];
        int pkw = __float_as_int(gw.w);
        int iw0 = pkw & 255, iw1 = (pkw >> 8) & 255;
        int lw0 = (pkw >> 16) & 255, lw1 = (pkw >> 24) & 255;
        float dwm = gw.x, dwp = gw.y, fw = gw.z;
        float aw0f = fabsf(dwm), aw1f = fabsf(dwp);

        float area[8]; int pos[8]; float tot = 0.0f;
        #pragma unroll
        for (int i = 0; i < 8; i++) {
            float aa = atah[i >> 1] * ((i & 1) ? aw1f : aw0f) + 1e-9f;
            area[i] = aa; tot += aa;
            pos[i] = bth[i >> 1] + ((i & 1) ? iw1 : iw0);
        }
        float rtot = 1.0f / tot;

        F4U A0 = P0, A1 = P1;
        {
            u64 am = pack2(dwm), ap = pack2(dwp);
            fma2(A0.u[0], am, c6a[4].u[0]); fma2(A0.u[1], am, c6a[4].u[1]);
            fma2(A1.u[0], am, c6b[4].u[0]); fma2(A1.u[1], am, c6b[4].u[1]);
            fma2(A0.u[0], ap, c6a[5].u[0]); fma2(A0.u[1], ap, c6a[5].u[1]);
            fma2(A1.u[0], ap, c6b[5].u[0]); fma2(A1.u[1], ap, c6b[5].u[1]);
        }

        __half2 hacc0 = __float2half2_rn(0.0f), hacc1 = hacc0, hacc2 = hacc0, hacc3 = hacc0;
        #pragma unroll
        for (int i = 0; i < 8; i++) {
            __half2 wp = __float2half2_rn(area[7 - i]);
            uint4 qv = *(const uint4*)(d_Qh + ((size_t)(i * NPOS + pos[i]) << 8) + ch);
            hacc0 = __hfma2(bits_h2(qv.x), wp, hacc0);
            hacc1 = __hfma2(bits_h2(qv.y), wp, hacc1);
            hacc2 = __hfma2(bits_h2(qv.z), wp, hacc2);
            hacc3 = __hfma2(bits_h2(qv.w), wp, hacc3);
        }
        float2 qf0 = __half22float2(hacc0);
        float2 qf1 = __half22float2(hacc1);
        float2 qf2 = __half22float2(hacc2);
        float2 qf3 = __half22float2(hacc3);
        __half2 xh0 = __floats2half2_rn(fmaf(qf0.x, rtot, A0.f[0]), fmaf(qf0.y, rtot, A0.f[1]));
        __half2 xh1 = __floats2half2_rn(fmaf(qf1.x, rtot, A0.f[2]), fmaf(qf1.y, rtot, A0.f[3]));
        __half2 xh2 = __floats2half2_rn(fmaf(qf2.x, rtot, A1.f[0]), fmaf(qf2.y, rtot, A1.f[1]));
        __half2 xh3 = __floats2half2_rn(fmaf(qf3.x, rtot, A1.f[2]), fmaf(qf3.y, rtot, A1.f[3]));
        float2 g0 = __half22float2(gelu_h2(xh0));
        float2 g1 = __half22float2(gelu_h2(xh1));
        float2 g2 = __half22float2(gelu_h2(xh2));
        float2 g3 = __half22float2(gelu_h2(xh3));

        float s0 = f2a[0].x * g0.x + f2a[0].y * g0.y + f2a[0].z * g1.x + f2a[0].w * g1.y
                 + f2b[0].x * g2.x + f2b[0].y * g2.y + f2b[0].z * g3.x + f2b[0].w * g3.y;
        float s1 = f2a[1].x * g0.x + f2a[1].y * g0.y + f2a[1].z * g1.x + f2a[1].w * g1.y
                 + f2b[1].x * g2.x + f2b[1].y * g2.y + f2b[1].z * g3.x + f2b[1].w * g3.y;
        float s2 = f2a[2].x * g0.x + f2a[2].y * g0.y + f2a[2].z * g1.x + f2a[2].w * g1.y
                 + f2b[2].x * g2.x + f2b[2].y * g2.y + f2b[2].z * g3.x + f2b[2].w * g3.y;

        if (lane < 8) {
            float wt = wt_th * (jw ? fw : 1.0f - fw);
            int p = p_th + (jw ? lw1 : lw0);
            s0 += wt * d_sc3[p];
            s1 += wt * d_sc3[NPOS + p];
            s2 += wt * d_sc3[2 * NPOS + p];
        }
        s0 += __shfl_xor_sync(0xffffffffu, s0, 16);
        s1 += __shfl_xor_sync(0xffffffffu, s1, 16);
        s2 += __shfl_xor_sync(0xffffffffu, s2, 16);
        s0 += __shfl_xor_sync(0xffffffffu, s0, 8);
        s1 += __shfl_xor_sync(0xffffffffu, s1, 8);
        s2 += __shfl_xor_sync(0xffffffffu, s2, 8);
        float v = (lane < 8) ? s0 : ((lane < 16) ? s1 : s2);
        v += __shfl_xor_sync(0xffffffffu, v, 4);
        v += __shfl_xor_sync(0xffffffffu, v, 2);
        v += __shfl_xor_sync(0xffffffffu, v, 1);
        if ((lane & 7) == 0 && lane < 24) {
            out[(lane >> 3) * NVOX + vbase + k] = v + obl;
        }
    }
}

extern "C" void kernel_launch(void* const* d_in, const int* in_sizes, int n_in,
                              void* d_out, int out_size) {
    const float* feat    = (const float*)d_in[0];
    const float* dw1_w   = (const float*)d_in[1];
    const float* dw1_b   = (const float*)d_in[2];
    const float* pw1_w   = (const float*)d_in[3];
    const float* pw1_b   = (const float*)d_in[4];
    const float* fc1_w   = (const float*)d_in[5];
    const float* fc1_b   = (const float*)d_in[6];
    const float* fc2_w   = (const float*)d_in[7];
    const float* fc2_b   = (const float*)d_in[8];
    const float* sc_dw_w = (const float*)d_in[9];
    const float* sc_dw_b = (const float*)d_in[10];
    const float* sc_pw_w = (const float*)d_in[11];
    const float* sc_pw_b = (const float*)d_in[12];
    float* out = (float*)d_out;

    k_prep<<<310, 256>>>(feat, dw1_w, dw1_b, pw1_w, pw1_b, fc1_w);
    k_phaseA_mma<<<1240, 256>>>(fc1_w, fc1_b, feat,
                                sc_dw_w, sc_dw_b, sc_pw_w, sc_pw_b);
    k_combine<<<600, 256>>>(fc2_w, fc2_b, out);
}